// round 7
// baseline (speedup 1.0000x reference)
#include <cuda_runtime.h>
#include <math.h>

#define BDIM 256
#define LDIM 8192
#define EDIM 64
#define NP   2731      // patch-start candidates (multiples of 3)
#define NQ   2736      // cs3 entries (q >= NP clamped to total)
#define NBINS 68       // 0..12 len3, 16..64 len12, 66 dummy
#define LOG2_9 3.169925001442312f

// kernel A config: 4 segments/row, 256 threads, 8 tokens/thread
#define ANT 256
#define ATPT 8
#define ASEG 4
#define ASEGTOK 2048

// kernel B config
#define BNT 256
#define BCH 43
#define BNCH 64

__device__ unsigned char  g_nxt[BDIM * NQ];
__device__ unsigned short g_cs3[BDIM * NQ];     // segment-local prefix sums
__device__ int            g_segsum[BDIM * ASEG];

// ============================ Kernel A: entropy + nxt + local cs3 ============
__global__ void __launch_bounds__(ANT, 6)
ka_entropy(const int* __restrict__ x, float* __restrict__ out)
{
    __shared__ unsigned int pubLo[ANT];
    __shared__ unsigned int pubHi[ANT];
    __shared__ unsigned int pubC[ANT];
    __shared__ float term[160];          // boundary LUT (bit-exact ref path)
    __shared__ float clrep[12 * 32];     // c*log2(c), per-lane replicated
    __shared__ float dlrep[12 * 32];     // delta LUT, per-lane replicated
    __shared__ int wscan[8];

    const int tid = threadIdx.x;
    const int lane = tid & 31;
    const int wid = tid >> 5;
    const int seg = blockIdx.x & (ASEG - 1);
    const int row = blockIdx.x >> 2;
    const int s0 = seg * ASEGTOK;
    const int p0 = s0 + tid * ATPT;
    const int* xr = x + (size_t)row * LDIM;

    int4 va = *(const int4*)(xr + p0);
    int4 vb = *(const int4*)(xr + p0 + 4);
    unsigned int tw0 = (unsigned)va.x | ((unsigned)va.y << 8) |
                       ((unsigned)va.z << 16) | ((unsigned)va.w << 24);
    unsigned int tw1 = (unsigned)vb.x | ((unsigned)vb.y << 8) |
                       ((unsigned)vb.z << 16) | ((unsigned)vb.w << 24);
    int localSum = va.x + va.y + va.z + va.w + vb.x + vb.y + vb.z + vb.w;
    pubLo[tid] = tw0; pubHi[tid] = tw1; pubC[tid] = tw1 & 0xFFu;

    if (tid < 160) {
        int t = tid >> 4, c = tid & 15;
        float v = 0.0f;
        if (t >= 1 && c <= t) { float pv = (float)c / (float)t; v = -(pv * log2f(pv + 1e-12f)); }
        term[tid] = v;
    }
    for (int i = tid; i < 384; i += ANT) {
        int c = i >> 5;
        float cl  = (c >= 1 && c <= 10) ? (float)c * log2f((float)c) : 0.0f;
        float clm = (c >= 2 && c <= 10) ? (float)(c - 1) * log2f((float)(c - 1)) : 0.0f;
        clrep[i] = cl;
        dlrep[i] = (c >= 1 && c <= 10) ? (cl - clm) : 0.0f;
    }
    __syncthreads();

    // halo (block-edge threads read global; row edges use boundary path)
    const bool rowFirst = (seg == 0 && tid == 0);
    const bool rowLast  = (seg == ASEG - 1 && tid == ANT - 1);
    unsigned int pm = 0, ep = 0, ep4 = 0;
    if (tid > 0) pm = pubHi[tid - 1];
    else if (seg > 0)
        pm = (unsigned)xr[p0-4] | ((unsigned)xr[p0-3] << 8) |
             ((unsigned)xr[p0-2] << 16) | ((unsigned)xr[p0-1] << 24);
    if (tid < ANT - 1) { ep = pubLo[tid + 1]; ep4 = pubC[tid + 1]; }
    else if (seg < ASEG - 1) {
        ep = (unsigned)xr[p0+8] | ((unsigned)xr[p0+9] << 8) |
             ((unsigned)xr[p0+10] << 16) | ((unsigned)xr[p0+11] << 24);
        ep4 = (unsigned)xr[p0+12];
    }

    // block scan of localSum (prefix within segment)
    int base;
    {
        int v = localSum;
        #pragma unroll
        for (int d = 1; d < 32; d <<= 1) {
            int n = __shfl_up_sync(0xffffffffu, v, d);
            if (lane >= d) v += n;
        }
        if (lane == 31) wscan[wid] = v;
        __syncthreads();
        if (tid < 8) {
            int wv = wscan[tid];
            #pragma unroll
            for (int d = 1; d < 8; d <<= 1) {
                int n = __shfl_up_sync(0xffu, wv, d);
                if (tid >= d) wv += n;
            }
            wscan[tid] = wv;
        }
        __syncthreads();
        base = v - localSum + ((wid > 0) ? wscan[wid - 1] : 0);
    }

    auto tok = [&](int idx) -> unsigned int {
        if (idx < 0)         return (pm >> ((idx + 4) * 8)) & 0xFFu;
        else if (idx < ATPT) return ((idx < 4 ? tw0 : tw1) >> ((idx & 3) * 8)) & 0xFFu;
        else if (idx < 12)   return (ep >> ((idx - 8) * 8)) & 0xFFu;
        else                 return ep4;
    };

    unsigned int packed = 0;
    #pragma unroll
    for (int i = 0; i <= 4; i++) packed += 1u << (tok(i) << 2);
    if (!rowFirst) {
        #pragma unroll
        for (int i = -4; i < 0; i++) packed += 1u << (tok(i) << 2);
    }

    const float* cl_lane = clrep + lane;
    const float* dl_lane = dlrep + lane;
    float S = 0.0f;
    {
        unsigned int pk = packed;
        #pragma unroll
        for (int c5 = 0; c5 < 5; c5++) { S += cl_lane[(pk & 15u) << 5]; pk >>= 4; }
    }

    int r0 = (3 - (p0 % 3)) % 3;
    int q = (p0 + r0) / 3;
    unsigned char* nrow = g_nxt + row * NQ;
    unsigned short* crow = g_cs3 + row * NQ;
    float4* outE4 = (float4*)(out + (size_t)BDIM * EDIM + (size_t)row * LDIM + p0);
    float4 stage;
    int run = base;

    #pragma unroll
    for (int k = 0; k < ATPT; k++) {
        float e = fmaf(-(1.0f / 9.0f), S, LOG2_9);
        if ((rowFirst && k < 4) || (rowLast && k >= ATPT - 4)) {
            int p = p0 + k;
            int wl = max(0, p - 4), wh = min(LDIM - 1, p + 4);
            int t = wh - wl + 1;
            const float* tb = term + (t << 4);
            unsigned int pk2 = packed;
            e  = tb[pk2 & 15]; pk2 >>= 4;
            e += tb[pk2 & 15]; pk2 >>= 4;
            e += tb[pk2 & 15]; pk2 >>= 4;
            e += tb[pk2 & 15]; pk2 >>= 4;
            e += tb[pk2 & 15];
        }
        if ((k & 3) == 0) stage.x = e;
        else if ((k & 3) == 1) stage.y = e;
        else if ((k & 3) == 2) stage.z = e;
        else { stage.w = e; outE4[k >> 2] = stage; }
        if ((k % 3) == r0) { nrow[q] = (e > 1.5f) ? (unsigned char)1 : (unsigned char)4; q++; }
        run += (int)tok(k);
        int idx = p0 + k + 1;
        if (idx % 3 == 0) crow[idx / 3] = (unsigned short)run;
        // slide: remove token p-4 first (counts stay <= 9), then add token p+5
        if (!(rowFirst && k < 4)) {
            unsigned int b = tok(k - 4);
            unsigned int sh = b << 2;
            unsigned int cb = (packed >> sh) & 15u;
            S -= dl_lane[cb << 5];
            packed -= 1u << sh;
        }
        if (!(rowLast && k >= ATPT - 5)) {
            unsigned int a = tok(k + 5);
            unsigned int sh = a << 2;
            unsigned int ca = (packed >> sh) & 15u;
            S += dl_lane[(ca + 1u) << 5];
            packed += 1u << sh;
        }
    }
    if (tid == ANT - 1) g_segsum[row * ASEG + seg] = run;
}

// ============================ Kernel B: walk + histogram + MLP ===============
__global__ void __launch_bounds__(BNT)
kb_walk(const float* __restrict__ w1, const float* __restrict__ b1,
        const float* __restrict__ w2, const float* __restrict__ b2,
        float* __restrict__ out)
{
    __shared__ float w2s[EDIM * 65];
    __shared__ unsigned short cs3[NQ];
    __shared__ unsigned char nxt[NQ + 16];
    __shared__ unsigned char nxt2[NQ + 16];
    __shared__ unsigned char nxt4[NQ + 16];
    __shared__ unsigned int exitsW[BNCH];
    __shared__ unsigned int mfull[BNCH];
    __shared__ unsigned char esel[BNCH + 4];
    __shared__ int histW[2][NBINS];
    __shared__ int NvW[2];
    __shared__ int tailS, tailLen;
    __shared__ float hsum[EDIM];

    const int tid = threadIdx.x;
    const int lane = tid & 31;
    const int wid = tid >> 5;
    const int row = blockIdx.x;

    // w2 -> smem via cp.async (padded rows), fire-and-forget
    #pragma unroll
    for (int r = 0; r < 16; r++) {
        int i = tid + r * BNT;
        unsigned int dst = (unsigned int)__cvta_generic_to_shared(
            &w2s[(i >> 6) * 65 + (i & 63)]);
        asm volatile("cp.async.ca.shared.global [%0], [%1], 4;\n"
                     :: "r"(dst), "l"(w2 + i));
    }
    asm volatile("cp.async.commit_group;\n" ::: "memory");

    float wv1 = 0.0f, bv1 = 0.0f, bv2 = 0.0f;
    if (tid < EDIM) { wv1 = w1[tid]; bv1 = b1[tid]; bv2 = b2[tid]; }

    // load nxt (word copies; row base NQ=2736 is 4B aligned)
    {
        const unsigned int* src = (const unsigned int*)(g_nxt + row * NQ);
        unsigned int* dst = (unsigned int*)nxt;
        #pragma unroll
        for (int i = tid; i < NQ / 4; i += BNT) dst[i] = src[i];
    }
    // segment offsets -> full cs3
    int o1 = g_segsum[row * ASEG + 0];
    int o2 = o1 + g_segsum[row * ASEG + 1];
    int o3 = o2 + g_segsum[row * ASEG + 2];
    int total = o3 + g_segsum[row * ASEG + 3];
    {
        const unsigned short* src = g_cs3 + row * NQ;
        for (int q = tid; q < NQ; q += BNT) {
            int v;
            if (q == 0) v = 0;
            else if (q >= NP) v = total;
            else {
                int s = (3 * q - 1) >> 11;      // which segment wrote q
                int off = (s == 0) ? 0 : ((s == 1) ? o1 : ((s == 2) ? o2 : o3));
                v = (int)src[q] + off;
            }
            cs3[q] = (unsigned short)v;
        }
    }
    for (int i = tid; i < 2 * NBINS; i += BNT) ((int*)histW)[i] = 0;
    if (tid == 0) { tailLen = 0; tailS = 0; NvW[0] = 0; NvW[1] = 0; }
    __syncthreads();

    // nxt2
    for (int p = tid; p < NP; p += BNT) {
        int u = nxt[p];
        int qq = p + u;
        nxt2[p] = (unsigned char)(u + ((qq < NP) ? (int)nxt[qq] : 4));
    }
    __syncthreads();
    // nxt4
    for (int p = tid; p < NP; p += BNT) {
        int u2 = nxt2[p];
        int q2 = p + u2;
        nxt4[p] = (unsigned char)(u2 + ((q2 < NP) ? (int)nxt2[q2] : 8));
    }
    __syncthreads();

    // speculative walks: 64 chunks x 4 entries = all 256 threads
    {
        int chunk = tid >> 2, e = tid & 3;
        int p = chunk * BCH + e;
        int pend = min((chunk + 1) * BCH, NP);
        while (p + (int)nxt4[p] < pend) p += (int)nxt4[p];
        if (p < pend) {
            int u2 = (int)nxt2[p];
            if (p + u2 < pend) p += u2;
            while (p < pend) p += (int)nxt[p];
        }
        ((unsigned char*)exitsW)[tid] = (unsigned char)(p - pend);
    }
    __syncthreads();

    // map scans (2 warps)
    if (tid < BNCH) {
        unsigned int m = exitsW[tid];
        #pragma unroll
        for (int d = 1; d < 32; d <<= 1) {
            unsigned int pmv = __shfl_up_sync(0xffffffffu, m, d);
            if (lane >= d) {
                unsigned int sel = (pmv & 0x3u) | ((pmv >> 4) & 0x30u) |
                                   ((pmv >> 8) & 0x300u) | ((pmv >> 12) & 0x3000u);
                m = __byte_perm(m, 0, sel);
            }
        }
        mfull[tid] = m;
    }
    __syncthreads();

    // entry offsets
    if (tid < BNCH) {
        if (tid == 0) esel[0] = 0;
        if (tid < BNCH - 1) {
            unsigned int Ew = (tid >= 32) ? (mfull[31] & 3u) : 0u;
            esel[tid + 1] = (unsigned char)((mfull[tid] >> (8 * Ew)) & 3u);
        }
    }
    __syncthreads();

    // real walk: 64 threads, 11 fixed trips, 4 patches/trip, match_any hist
    if (tid < BNCH) {
        int p = tid * BCH + (int)esel[tid];
        int pend = min((tid + 1) * BCH, NP);
        int nv = 0;
        int* hw = histW[wid];

        #pragma unroll 1
        for (int it = 0; it < 11; it++) {
            int key0 = 66, key1 = 66, key2 = 66, key3 = 66;
            if (p < pend) {
                int u1 = (int)nxt[p];
                int u2 = (int)nxt2[p];
                {
                    int qn = p + u1;
                    int j = min(3 * qn, LDIM);
                    int len = j - 3 * p;
                    int S = (int)cs3[qn] - (int)cs3[p];
                    nv++;
                    if (len == 3) key0 = S; else if (len == 12) key0 = 16 + S;
                    else { tailS = S; tailLen = len; }
                }
                int p1 = p + u1;
                if (p1 < pend) {
                    int ul = u2 - u1;
                    int qn = p1 + ul;
                    int j = min(3 * qn, LDIM);
                    int len = j - 3 * p1;
                    int S = (int)cs3[qn] - (int)cs3[p1];
                    nv++;
                    if (len == 3) key1 = S; else if (len == 12) key1 = 16 + S;
                    else { tailS = S; tailLen = len; }
                    int p2 = p + u2;
                    if (p2 < pend) {
                        int u3 = (int)nxt[p2];
                        int u4 = (int)nxt2[p2];
                        {
                            int qn2 = p2 + u3;
                            int j2 = min(3 * qn2, LDIM);
                            int len2 = j2 - 3 * p2;
                            int S2 = (int)cs3[qn2] - (int)cs3[p2];
                            nv++;
                            if (len2 == 3) key2 = S2; else if (len2 == 12) key2 = 16 + S2;
                            else { tailS = S2; tailLen = len2; }
                        }
                        int p3 = p2 + u3;
                        if (p3 < pend) {
                            int ul2 = u4 - u3;
                            int qn3 = p3 + ul2;
                            int j3 = min(3 * qn3, LDIM);
                            int len3 = j3 - 3 * p3;
                            int S3 = (int)cs3[qn3] - (int)cs3[p3];
                            nv++;
                            if (len3 == 3) key3 = S3; else if (len3 == 12) key3 = 16 + S3;
                            else { tailS = S3; tailLen = len3; }
                            p = p2 + u4;
                        } else p = p3;
                    } else p = p2;
                } else p = p1;
            }
            unsigned int g;
            g = __match_any_sync(0xffffffffu, key0);
            if (key0 != 66 && (__ffs(g) - 1) == lane) hw[key0] += __popc(g);
            g = __match_any_sync(0xffffffffu, key1);
            if (key1 != 66 && (__ffs(g) - 1) == lane) hw[key1] += __popc(g);
            g = __match_any_sync(0xffffffffu, key2);
            if (key2 != 66 && (__ffs(g) - 1) == lane) hw[key2] += __popc(g);
            g = __match_any_sync(0xffffffffu, key3);
            if (key3 != 66 && (__ffs(g) - 1) == lane) hw[key3] += __popc(g);
        }
        #pragma unroll
        for (int d = 16; d > 0; d >>= 1) nv += __shfl_down_sync(0xffffffffu, nv, d);
        if (lane == 0) NvW[wid] = nv;
    }
    asm volatile("cp.async.wait_group 0;\n" ::: "memory");
    __syncthreads();

    // merge per-warp histograms
    if (tid < NBINS) histW[0][tid] += histW[1][tid];
    __syncthreads();

    // hsum[e] = mean over valid patches of relu(mean*w1[e]+b1[e])
    if (tid < EDIM) {
        float acc = 0.0f;
        #pragma unroll
        for (int s = 0; s <= 12; s++) {
            int c = histW[0][s];
            acc += (float)c * fmaxf(fmaf((float)s / 3.0f, wv1, bv1), 0.0f);
        }
        #pragma unroll
        for (int s = 0; s <= 48; s++) {
            int c = histW[0][16 + s];
            acc += (float)c * fmaxf(fmaf((float)s / 12.0f, wv1, bv1), 0.0f);
        }
        if (tailLen > 0)
            acc += fmaxf(fmaf((float)tailS / (float)tailLen, wv1, bv1), 0.0f);
        int Nv = NvW[0] + NvW[1];
        hsum[tid] = acc / (float)Nv;
    }
    __syncthreads();

    // vec = hbar @ w2^T + b2
    if (tid < EDIM) {
        const float* wrow = w2s + tid * 65;
        float v = bv2;
        #pragma unroll
        for (int e = 0; e < EDIM; e++) v = fmaf(hsum[e], wrow[e], v);
        out[(size_t)row * EDIM + tid] = v;
    }
}

extern "C" void kernel_launch(void* const* d_in, const int* in_sizes, int n_in,
                              void* d_out, int out_size)
{
    const int*   x  = (const int*)d_in[0];
    const float* w1 = (const float*)d_in[1];
    const float* b1 = (const float*)d_in[2];
    const float* w2 = (const float*)d_in[3];
    const float* b2 = (const float*)d_in[4];
    float* out = (float*)d_out;

    ka_entropy<<<BDIM * ASEG, ANT>>>(x, out);
    kb_walk<<<BDIM, BNT>>>(w1, b1, w2, b2, out);
}

// round 9
// speedup vs baseline: 1.0743x; 1.0743x over previous
#include <cuda_runtime.h>
#include <math.h>

#define BDIM 256
#define LDIM 8192
#define EDIM 64
#define NP   2731      // patch-start candidates (multiples of 3): ceil(8192/3)
#define NQ   2736      // cs3 entries (q >= NP clamped to total)
#define NTHREADS 512
#define TPT 16         // tokens per thread
#define PPT 6          // p-positions per thread in the scan (512*6=3072 >= NP)
#define NXTPAD 3088    // nxt sized past 3072 apply range
#define NBINS 68       // 0..12 len3, 16..64 len12
#define NHIST 4
#define LOG2_9 3.169925001442312f
#define MIDENT 0x8421u // 4x4 boolean identity (bits 0,5,10,15)

struct SmemLayout {
    float w2s[EDIM * 65];            // padded rows (cp.async filled)
    unsigned short cs3[NQ];          // prefix sums at multiples of 3 (+clamped tail)
    unsigned int nbA[NTHREADS];      // each thread's tw[3]
    unsigned int nbB[NTHREADS];      // each thread's tw[0]
    unsigned int nbC[NTHREADS];      // token p0+4
    unsigned char nxt[NXTPAD];       // step (1 or 4), padded
    float term[160];                 // boundary entropy LUT (bit-exact ref path)
    float clrep[12 * 32];            // c*log2(c), per-lane replicated
    float dlrep[12 * 32];            // delta LUT, per-lane replicated
    unsigned int wtotM[16];          // per-warp composite matrices
    unsigned int wpreM[16];          // exclusive warp prefixes
    int hist[NHIST][NBINS];
    int NvTot;
    int wscan[16];
    int tailS, tailLen;
    float hsum[EDIM];
};

// C = E ∘ M where E is elementary with bits A (use b[p-1]) and B (use b[p-4])
__device__ __forceinline__ unsigned int ecomp(unsigned int M, unsigned int A, unsigned int B) {
    unsigned int row0 = (A ? (M & 15u) : 0u) | (B ? ((M >> 12) & 15u) : 0u);
    return ((M << 4) & 0xFFF0u) | row0;
}
// C = M2 ∘ M1 (apply M1 first): row_i(C) = OR_{k in row_i(M2)} row_k(M1)
__device__ __forceinline__ unsigned int mcomp(unsigned int m2, unsigned int m1) {
    unsigned int r0 = m1 & 15u, r1 = (m1 >> 4) & 15u, r2 = (m1 >> 8) & 15u, r3 = (m1 >> 12) & 15u;
    unsigned int c = 0;
    #pragma unroll
    for (int i = 0; i < 4; i++) {
        unsigned int row = (m2 >> (4 * i)) & 15u;
        unsigned int ci = ((row & 1u) ? r0 : 0u) | ((row & 2u) ? r1 : 0u) |
                          ((row & 4u) ? r2 : 0u) | ((row & 8u) ? r3 : 0u);
        c |= ci << (4 * i);
    }
    return c;
}

__global__ void __launch_bounds__(NTHREADS, 2)
ep_kernel(const int* __restrict__ x,
          const float* __restrict__ w1,
          const float* __restrict__ b1,
          const float* __restrict__ w2,
          const float* __restrict__ b2,
          float* __restrict__ out)
{
    extern __shared__ unsigned char raw[];
    SmemLayout* sm = (SmemLayout*)raw;
    const int tid = threadIdx.x;
    const int lane = tid & 31;
    const int wid = tid >> 5;
    const int row = blockIdx.x;
    const int p0 = tid * TPT;

    // ---- stage own 16 tokens into registers; publish neighbor words ----
    const int4* xv = (const int4*)(x + (size_t)row * LDIM) + tid * 4;
    unsigned int tw[4];
    int localSum = 0;
    #pragma unroll
    for (int k = 0; k < 4; k++) {
        int4 v = xv[k];
        unsigned int w = (unsigned int)v.x | ((unsigned int)v.y << 8) |
                         ((unsigned int)v.z << 16) | ((unsigned int)v.w << 24);
        tw[k] = w;
        localSum += v.x + v.y + v.z + v.w;
    }
    sm->nbA[tid] = tw[3];
    sm->nbB[tid] = tw[0];
    sm->nbC[tid] = tw[1] & 0xFF;

    // ---- prefetch w1/b1/b2 into registers ----
    float wv1 = 0.0f, bv1 = 0.0f, bv2 = 0.0f;
    if (tid < EDIM) { wv1 = w1[tid]; bv1 = b1[tid]; bv2 = b2[tid]; }

    // ---- w2 -> smem via cp.async, fire-and-forget ----
    {
        #pragma unroll
        for (int r = 0; r < 8; r++) {
            int i = tid + r * NTHREADS;
            unsigned int dst = (unsigned int)__cvta_generic_to_shared(
                &sm->w2s[(i >> 6) * 65 + (i & 63)]);
            const float* src = w2 + i;
            asm volatile("cp.async.ca.shared.global [%0], [%1], 4;\n"
                         :: "r"(dst), "l"(src));
        }
        asm volatile("cp.async.commit_group;\n" ::: "memory");
    }

    // ---- LUTs & init ----
    if (tid < 160) {
        int t = tid >> 4, c = tid & 15;
        float v = 0.0f;
        if (t >= 1 && c <= t) { float pv = (float)c / (float)t; v = -(pv * log2f(pv + 1e-12f)); }
        sm->term[tid] = v;
    }
    if (tid >= 160 && tid < 160 + 384) {
        int i = tid - 160;
        int c = i >> 5;
        float cl  = (c >= 1 && c <= 10) ? (float)c * log2f((float)c) : 0.0f;
        float clm = (c >= 2 && c <= 10) ? (float)(c - 1) * log2f((float)(c - 1)) : 0.0f;
        sm->clrep[i] = cl;
        sm->dlrep[i] = (c >= 1 && c <= 10) ? (cl - clm) : 0.0f;
    }
    for (int i = tid; i < NHIST * NBINS; i += NTHREADS) ((int*)sm->hist)[i] = 0;
    {   // pad nxt beyond NP (values irrelevant, avoids OOB in scan phase)
        int i = NP + tid;
        if (i < NXTPAD) sm->nxt[i] = 4;
    }
    if (tid == 0) { sm->tailLen = 0; sm->tailS = 0; sm->NvTot = 0; }
    __syncthreads();

    // ---- block scan of localSum; write cs3 (multiples of 3 only) ----
    {
        int v = localSum;
        #pragma unroll
        for (int d = 1; d < 32; d <<= 1) {
            int n = __shfl_up_sync(0xffffffffu, v, d);
            if (lane >= d) v += n;
        }
        if (lane == 31) sm->wscan[wid] = v;
        __syncthreads();
        if (tid < 16) {
            int wv = sm->wscan[tid];
            #pragma unroll
            for (int d = 1; d < 16; d <<= 1) {
                int n = __shfl_up_sync(0xffffu, wv, d);
                if (tid >= d) wv += n;
            }
            sm->wscan[tid] = wv;
        }
        __syncthreads();
        int base = v - localSum + ((wid > 0) ? sm->wscan[wid - 1] : 0);
        if (tid == 0) sm->cs3[0] = 0;
        int run = base;
        #pragma unroll
        for (int k = 0; k < TPT; k++) {
            run += (int)((tw[k >> 2] >> ((k & 3) * 8)) & 0xFF);
            int idx = p0 + k + 1;
            if (idx % 3 == 0) sm->cs3[idx / 3] = (unsigned short)run;
        }
        if (tid == NTHREADS - 1) {
            #pragma unroll
            for (int q = NP; q < NQ; q++) sm->cs3[q] = (unsigned short)run;
        }
    }

    // ---- entropy: incremental S = sum(c*log2 c), 2 LDS per position ----
    {
        const bool firstT = (tid == 0);
        const bool lastT = (tid == NTHREADS - 1);
        unsigned int pm = firstT ? 0u : sm->nbA[tid - 1];     // tokens p0-4..p0-1
        unsigned int ep = lastT ? 0u : sm->nbB[tid + 1];      // tokens p0+16..p0+19
        unsigned int ep4 = lastT ? 0u : sm->nbC[tid + 1];     // token p0+20

        auto tok = [&](int idx) -> unsigned int {
            if (idx < 0)        return (pm >> ((idx + 4) * 8)) & 0xFF;
            else if (idx < TPT) return (tw[idx >> 2] >> ((idx & 3) * 8)) & 0xFF;
            else if (idx < 20)  return (ep >> ((idx - TPT) * 8)) & 0xFF;
            else                return ep4;
        };

        unsigned int packed = 0;
        #pragma unroll
        for (int i = 0; i <= 4; i++) packed += 1u << (tok(i) << 2);
        if (!firstT) {
            #pragma unroll
            for (int i = -4; i < 0; i++) packed += 1u << (tok(i) << 2);
        }

        const float* cl_lane = sm->clrep + lane;
        const float* dl_lane = sm->dlrep + lane;
        float S = 0.0f;
        {
            unsigned int pk = packed;
            #pragma unroll
            for (int c5 = 0; c5 < 5; c5++) { S += cl_lane[(pk & 15u) << 5]; pk >>= 4; }
        }

        int r0 = (3 - (p0 % 3)) % 3;
        int q = (p0 + r0) / 3;
        float4* outE4 = (float4*)(out + (size_t)BDIM * EDIM + (size_t)row * LDIM + p0);
        float4 stage;

        #pragma unroll
        for (int k = 0; k < TPT; k++) {
            float e = fmaf(-(1.0f / 9.0f), S, LOG2_9);
            if ((firstT && k < 4) || (lastT && k >= TPT - 4)) {
                int p = p0 + k;
                int wl = max(0, p - 4), wh = min(LDIM - 1, p + 4);
                int t = wh - wl + 1;
                const float* tb = sm->term + (t << 4);
                unsigned int pk2 = packed;
                e  = tb[pk2 & 15]; pk2 >>= 4;
                e += tb[pk2 & 15]; pk2 >>= 4;
                e += tb[pk2 & 15]; pk2 >>= 4;
                e += tb[pk2 & 15]; pk2 >>= 4;
                e += tb[pk2 & 15];
            }
            if ((k & 3) == 0) stage.x = e;
            else if ((k & 3) == 1) stage.y = e;
            else if ((k & 3) == 2) stage.z = e;
            else { stage.w = e; outE4[k >> 2] = stage; }
            if ((k % 3) == r0) { sm->nxt[q] = (e > 1.5f) ? (unsigned char)1 : (unsigned char)4; q++; }
            if (!(firstT && k < 4)) {
                unsigned int b = tok(k - 4);
                unsigned int sh = b << 2;
                unsigned int cb = (packed >> sh) & 15u;
                S -= dl_lane[cb << 5];
                packed -= 1u << sh;
            }
            if (!(lastT && k >= TPT - 5)) {
                unsigned int a = tok(k + 5);
                unsigned int sh = a << 2;
                unsigned int ca = (packed >> sh) & 15u;
                S += dl_lane[(ca + 1u) << 5];
                packed += 1u << sh;
            }
        }
    }
    __syncthreads();

    // ---- patch-start scan: per-thread 6-step boolean matrix + warp scan ----
    // b[p] = (nxt[p-1]==1 && b[p-1]) || (p>=4 && nxt[p-4]==4 && b[p-4]); b[0]=1
    const int pstart = 1 + tid * PPT;
    {
        unsigned int M = MIDENT;
        #pragma unroll
        for (int k = 0; k < PPT; k++) {
            int p = pstart + k;
            unsigned int A = (sm->nxt[p - 1] == 1) ? 1u : 0u;
            unsigned int B = (p >= 4 && sm->nxt[p - 4] == 4) ? 1u : 0u;
            M = ecomp(M, A, B);
        }
        // warp inclusive scan (compose: later ∘ earlier)
        #pragma unroll
        for (int d = 1; d < 32; d <<= 1) {
            unsigned int pmv = __shfl_up_sync(0xffffffffu, M, d);
            if (lane >= d) M = mcomp(M, pmv);
        }
        if (lane == 31) sm->wtotM[wid] = M;
        // thread-exclusive within warp stays in register via shfl below after warp prefixes
        // stash inclusive in register for later
        // (store M per-thread? keep in reg)
        // we need it after barrier; keep in a variable:
        // fallthrough
        __syncthreads();
        if (tid < 16) {
            unsigned int m = sm->wtotM[tid];
            #pragma unroll
            for (int d = 1; d < 16; d <<= 1) {
                unsigned int pmv = __shfl_up_sync(0xffffu, m, d);
                if (tid >= d) m = mcomp(m, pmv);
            }
            sm->wpreM[tid] = m;   // inclusive warp prefix
        }
        __syncthreads();

        // exclusive composite for this thread
        unsigned int excl = __shfl_up_sync(0xffffffffu, M, 1);
        if (lane == 0) excl = MIDENT;
        unsigned int wpre = (wid > 0) ? sm->wpreM[wid - 1] : MIDENT;
        unsigned int exc = mcomp(excl, wpre);     // apply warp prefix first, then lanes before me
        // entry state = column 0 of exc (since s0 = e0 at p=1: b[0]=1, rest 0)
        unsigned int s = (exc & 1u) | ((exc >> 3) & 2u) | ((exc >> 6) & 4u) | ((exc >> 9) & 8u);

        // ---- apply + histogram ----
        int nv = 0;
        int* hw = sm->hist[wid & (NHIST - 1)];
        if (tid == 0) {   // bin p = 0 (always a patch start)
            int u = (int)sm->nxt[0];
            int S0 = (int)sm->cs3[u];     // cs3[0] = 0
            nv++;
            if (u == 1) atomicAdd(&hw[S0], 1);
            else        atomicAdd(&hw[16 + S0], 1);
        }
        unsigned char npm1 = sm->nxt[pstart - 1];
        #pragma unroll
        for (int k = 0; k < PPT; k++) {
            int p = pstart + k;
            unsigned char np = sm->nxt[p];
            unsigned int A = (npm1 == 1) ? 1u : 0u;
            unsigned int B = (p >= 4 && sm->nxt[p - 4] == 4) ? 1u : 0u;
            unsigned int b = (A & (s & 1u)) | (B & ((s >> 3) & 1u));
            s = ((s << 1) | b) & 15u;
            npm1 = np;
            if (b && p < NP) {
                int u = (int)np;
                int qn = p + u;
                int j = min(3 * qn, LDIM);
                int len = j - 3 * p;
                int Sv = (int)sm->cs3[qn] - (int)sm->cs3[p];
                nv++;
                if (len == 3)       atomicAdd(&hw[Sv], 1);
                else if (len == 12) atomicAdd(&hw[16 + Sv], 1);
                else { sm->tailS = Sv; sm->tailLen = len; }
            }
        }
        #pragma unroll
        for (int d = 16; d > 0; d >>= 1) nv += __shfl_down_sync(0xffffffffu, nv, d);
        if (lane == 0 && nv) atomicAdd(&sm->NvTot, nv);
    }
    asm volatile("cp.async.wait_group 0;\n" ::: "memory");
    __syncthreads();

    // ---- merge histograms into hist[0] ----
    if (tid < NBINS)
        sm->hist[0][tid] += sm->hist[1][tid] + sm->hist[2][tid] + sm->hist[3][tid];
    __syncthreads();

    // ---- hsum[e] = mean over valid patches of relu(mean*w1[e]+b1[e]) ----
    if (tid < EDIM) {
        float acc = 0.0f;
        #pragma unroll
        for (int s = 0; s <= 12; s++) {
            int c = sm->hist[0][s];
            acc += (float)c * fmaxf(fmaf((float)s / 3.0f, wv1, bv1), 0.0f);
        }
        #pragma unroll
        for (int s = 0; s <= 48; s++) {
            int c = sm->hist[0][16 + s];
            acc += (float)c * fmaxf(fmaf((float)s / 12.0f, wv1, bv1), 0.0f);
        }
        if (sm->tailLen > 0)
            acc += fmaxf(fmaf((float)sm->tailS / (float)sm->tailLen, wv1, bv1), 0.0f);
        sm->hsum[tid] = acc / (float)sm->NvTot;
    }
    __syncthreads();

    // ---- vec = hbar @ w2^T + b2 ----
    if (tid < EDIM) {
        const float* wrow = sm->w2s + tid * 65;
        float v = bv2;
        #pragma unroll
        for (int e = 0; e < EDIM; e++) v = fmaf(sm->hsum[e], wrow[e], v);
        out[(size_t)row * EDIM + tid] = v;
    }
}

extern "C" void kernel_launch(void* const* d_in, const int* in_sizes, int n_in,
                              void* d_out, int out_size)
{
    const int*   x  = (const int*)d_in[0];
    const float* w1 = (const float*)d_in[1];
    const float* b1 = (const float*)d_in[2];
    const float* w2 = (const float*)d_in[3];
    const float* b2 = (const float*)d_in[4];
    float* out = (float*)d_out;

    cudaFuncSetAttribute(ep_kernel, cudaFuncAttributeMaxDynamicSharedMemorySize,
                         (int)sizeof(SmemLayout));
    ep_kernel<<<BDIM, NTHREADS, sizeof(SmemLayout)>>>(x, w1, b1, w2, b2, out);
}

// round 14
// speedup vs baseline: 1.5389x; 1.4324x over previous
#include <cuda_runtime.h>
#include <math.h>

#define BDIM 256
#define LDIM 8192
#define EDIM 64
#define NP   2731      // patch-start candidates (multiples of 3): ceil(8192/3)
#define NQ   2736      // cs3 entries (q >= NP clamped to total)
#define CH   22        // chunk size in p-units (128 chunks cover 2731)
#define NCHUNK 128
#define NTHREADS 512
#define TPT 16         // tokens per thread
#define NBINS 68       // 0..12 len3, 16..64 len12, 66 dummy
#define NWALKW 4
#define LOG2_9 3.169925001442312f

struct SmemLayout {
    float w2s[EDIM * 65];            // padded rows (cp.async filled)
    unsigned short cs3[NQ];          // prefix sums at multiples of 3 (+clamped tail)
    unsigned int nbA[NTHREADS];      // each thread's tw[3]
    unsigned int nbB[NTHREADS];      // each thread's tw[0]
    unsigned int nbC[NTHREADS];      // token p0+4
    unsigned char nxt[NP + 8];       // step (1 or 4)
    unsigned char nxt2[NP + 8];
    unsigned char nxt4[NP + 8];
    float term[160];                 // boundary entropy LUT (bit-exact ref path)
    float clrep[12 * 32];            // c*log2(c), per-lane replicated
    float dlrep[12 * 32];            // delta LUT, per-lane replicated
    unsigned int exitsW[NCHUNK];
    unsigned int mfull[NCHUNK];
    unsigned char wtotE[8];
    unsigned char esel[NCHUNK + 4];
    int histW[NWALKW][NBINS];
    int NvW[NWALKW];
    int wscan[16];
    int tailS, tailLen;
    float hsum[EDIM];
};

__global__ void __launch_bounds__(NTHREADS, 2)
ep_kernel(const int* __restrict__ x,
          const float* __restrict__ w1,
          const float* __restrict__ b1,
          const float* __restrict__ w2,
          const float* __restrict__ b2,
          float* __restrict__ out)
{
    extern __shared__ unsigned char raw[];
    SmemLayout* sm = (SmemLayout*)raw;
    const int tid = threadIdx.x;
    const int lane = tid & 31;
    const int wid = tid >> 5;
    const int row = blockIdx.x;
    const int p0 = tid * TPT;

    // ---- stage own 16 tokens into registers; publish neighbor words ----
    const int4* xv = (const int4*)(x + (size_t)row * LDIM) + tid * 4;
    unsigned int tw[4];
    int localSum = 0;
    #pragma unroll
    for (int k = 0; k < 4; k++) {
        int4 v = xv[k];
        unsigned int w = (unsigned int)v.x | ((unsigned int)v.y << 8) |
                         ((unsigned int)v.z << 16) | ((unsigned int)v.w << 24);
        tw[k] = w;
        localSum += v.x + v.y + v.z + v.w;
    }
    sm->nbA[tid] = tw[3];
    sm->nbB[tid] = tw[0];
    sm->nbC[tid] = tw[1] & 0xFF;

    // ---- prefetch w1/b1/b2 into registers ----
    float wv1 = 0.0f, bv1 = 0.0f, bv2 = 0.0f;
    if (tid < EDIM) { wv1 = w1[tid]; bv1 = b1[tid]; bv2 = b2[tid]; }

    // ---- w2 -> smem via cp.async, fire-and-forget ----
    {
        #pragma unroll
        for (int r = 0; r < 8; r++) {
            int i = tid + r * NTHREADS;
            unsigned int dst = (unsigned int)__cvta_generic_to_shared(
                &sm->w2s[(i >> 6) * 65 + (i & 63)]);
            const float* src = w2 + i;
            asm volatile("cp.async.ca.shared.global [%0], [%1], 4;\n"
                         :: "r"(dst), "l"(src));
        }
        asm volatile("cp.async.commit_group;\n" ::: "memory");
    }

    // ---- LUTs & init ----
    if (tid < 160) {
        int t = tid >> 4, c = tid & 15;
        float v = 0.0f;
        if (t >= 1 && c <= t) { float pv = (float)c / (float)t; v = -(pv * log2f(pv + 1e-12f)); }
        sm->term[tid] = v;
    }
    if (tid >= 160 && tid < 160 + 384) {
        int i = tid - 160;
        int c = i >> 5;
        float cl  = (c >= 1 && c <= 10) ? (float)c * log2f((float)c) : 0.0f;
        float clm = (c >= 2 && c <= 10) ? (float)(c - 1) * log2f((float)(c - 1)) : 0.0f;
        sm->clrep[i] = cl;
        sm->dlrep[i] = (c >= 1 && c <= 10) ? (cl - clm) : 0.0f;
    }
    for (int i = tid; i < NWALKW * NBINS; i += NTHREADS) ((int*)sm->histW)[i] = 0;
    if (tid == 0) { sm->tailLen = 0; sm->tailS = 0; }
    if (tid < NWALKW) sm->NvW[tid] = 0;
    __syncthreads();

    // ---- block scan of localSum; write cs3 (multiples of 3 only) ----
    {
        int v = localSum;
        #pragma unroll
        for (int d = 1; d < 32; d <<= 1) {
            int n = __shfl_up_sync(0xffffffffu, v, d);
            if (lane >= d) v += n;
        }
        if (lane == 31) sm->wscan[wid] = v;
        __syncthreads();
        if (tid < 16) {
            int wv = sm->wscan[tid];
            #pragma unroll
            for (int d = 1; d < 16; d <<= 1) {
                int n = __shfl_up_sync(0xffffu, wv, d);
                if (tid >= d) wv += n;
            }
            sm->wscan[tid] = wv;
        }
        __syncthreads();
        int base = v - localSum + ((wid > 0) ? sm->wscan[wid - 1] : 0);
        if (tid == 0) sm->cs3[0] = 0;
        int run = base;
        #pragma unroll
        for (int k = 0; k < TPT; k++) {
            run += (int)((tw[k >> 2] >> ((k & 3) * 8)) & 0xFF);
            int idx = p0 + k + 1;
            if (idx % 3 == 0) sm->cs3[idx / 3] = (unsigned short)run;
        }
        if (tid == NTHREADS - 1) {
            #pragma unroll
            for (int q = NP; q < NQ; q++) sm->cs3[q] = (unsigned short)run;
        }
    }

    // ---- entropy: incremental S = sum(c*log2 c), 2 LDS per position ----
    {
        const bool firstT = (tid == 0);
        const bool lastT = (tid == NTHREADS - 1);
        unsigned int pm = firstT ? 0u : sm->nbA[tid - 1];     // tokens p0-4..p0-1
        unsigned int ep = lastT ? 0u : sm->nbB[tid + 1];      // tokens p0+16..p0+19
        unsigned int ep4 = lastT ? 0u : sm->nbC[tid + 1];     // token p0+20

        auto tok = [&](int idx) -> unsigned int {
            if (idx < 0)        return (pm >> ((idx + 4) * 8)) & 0xFF;
            else if (idx < TPT) return (tw[idx >> 2] >> ((idx & 3) * 8)) & 0xFF;
            else if (idx < 20)  return (ep >> ((idx - TPT) * 8)) & 0xFF;
            else                return ep4;
        };

        unsigned int packed = 0;
        #pragma unroll
        for (int i = 0; i <= 4; i++) packed += 1u << (tok(i) << 2);
        if (!firstT) {
            #pragma unroll
            for (int i = -4; i < 0; i++) packed += 1u << (tok(i) << 2);
        }

        const float* cl_lane = sm->clrep + lane;
        const float* dl_lane = sm->dlrep + lane;
        float S = 0.0f;
        {
            unsigned int pk = packed;
            #pragma unroll
            for (int c5 = 0; c5 < 5; c5++) { S += cl_lane[(pk & 15u) << 5]; pk >>= 4; }
        }

        int r0 = (3 - (p0 % 3)) % 3;
        int q = (p0 + r0) / 3;
        float4* outE4 = (float4*)(out + (size_t)BDIM * EDIM + (size_t)row * LDIM + p0);
        float4 stage;

        #pragma unroll
        for (int k = 0; k < TPT; k++) {
            float e = fmaf(-(1.0f / 9.0f), S, LOG2_9);
            if ((firstT && k < 4) || (lastT && k >= TPT - 4)) {
                int p = p0 + k;
                int wl = max(0, p - 4), wh = min(LDIM - 1, p + 4);
                int t = wh - wl + 1;
                const float* tb = sm->term + (t << 4);
                unsigned int pk2 = packed;
                e  = tb[pk2 & 15]; pk2 >>= 4;
                e += tb[pk2 & 15]; pk2 >>= 4;
                e += tb[pk2 & 15]; pk2 >>= 4;
                e += tb[pk2 & 15]; pk2 >>= 4;
                e += tb[pk2 & 15];
            }
            if ((k & 3) == 0) stage.x = e;
            else if ((k & 3) == 1) stage.y = e;
            else if ((k & 3) == 2) stage.z = e;
            else { stage.w = e; outE4[k >> 2] = stage; }
            if ((k % 3) == r0) { sm->nxt[q] = (e > 1.5f) ? (unsigned char)1 : (unsigned char)4; q++; }
            if (!(firstT && k < 4)) {
                unsigned int b = tok(k - 4);
                unsigned int sh = b << 2;
                unsigned int cb = (packed >> sh) & 15u;
                S -= dl_lane[cb << 5];
                packed -= 1u << sh;
            }
            if (!(lastT && k >= TPT - 5)) {
                unsigned int a = tok(k + 5);
                unsigned int sh = a << 2;
                unsigned int ca = (packed >> sh) & 15u;
                S += dl_lane[(ca + 1u) << 5];
                packed += 1u << sh;
            }
        }
    }
    __syncthreads();

    // ---- nxt2 ----
    for (int p = tid; p < NP; p += NTHREADS) {
        int u = sm->nxt[p];
        int qq = p + u;
        sm->nxt2[p] = (unsigned char)(u + ((qq < NP) ? (int)sm->nxt[qq] : 4));
    }
    __syncthreads();

    // ---- nxt4 ----
    for (int p = tid; p < NP; p += NTHREADS) {
        int u2 = sm->nxt2[p];
        int q2 = p + u2;
        sm->nxt4[p] = (unsigned char)(u2 + ((q2 < NP) ? (int)sm->nxt2[q2] : 8));
    }
    __syncthreads();

    // ---- speculative chunk walks: 128 chunks x 4 entries = all 512 threads ----
    {
        int chunk = tid >> 2, e = tid & 3;
        int p = chunk * CH + e;
        int pend = min((chunk + 1) * CH, NP);
        while (p + (int)sm->nxt4[p] < pend) p += (int)sm->nxt4[p];
        if (p < pend) {
            int u2 = (int)sm->nxt2[p];
            if (p + u2 < pend) p += u2;
            while (p < pend) p += (int)sm->nxt[p];
        }
        ((unsigned char*)sm->exitsW)[tid] = (unsigned char)(p - pend);
    }
    __syncthreads();

    // ---- warps 0-3: per-warp map scans ----
    if (tid < NCHUNK) {
        unsigned int m = sm->exitsW[tid];
        #pragma unroll
        for (int d = 1; d < 32; d <<= 1) {
            unsigned int pmv = __shfl_up_sync(0xffffffffu, m, d);
            if (lane >= d) {
                unsigned int sel = (pmv & 0x3u) | ((pmv >> 4) & 0x30u) |
                                   ((pmv >> 8) & 0x300u) | ((pmv >> 12) & 0x3000u);
                m = __byte_perm(m, 0, sel);
            }
        }
        sm->mfull[tid] = m;
    }
    __syncthreads();

    // ---- compose warp totals ----
    if (tid == 0) {
        unsigned char E = 0;
        sm->wtotE[0] = 0;
        #pragma unroll
        for (int w = 0; w < 3; w++) {
            unsigned int T = sm->mfull[w * 32 + 31];
            E = (unsigned char)((T >> (8 * E)) & 0x3u);
            sm->wtotE[w + 1] = E;
        }
    }
    __syncthreads();

    // ---- per-chunk entry offsets ----
    if (tid < NCHUNK) {
        if (tid == 0) sm->esel[0] = 0;
        if (tid < NCHUNK - 1) {
            unsigned int Ew = sm->wtotE[tid >> 5];
            sm->esel[tid + 1] = (unsigned char)((sm->mfull[tid] >> (8 * Ew)) & 0x3u);
        }
    }
    __syncthreads();

    // ---- real walk: 128 threads, 6 fixed trips, 4 patches/trip, match_any hist ----
    if (tid < NCHUNK) {
        int p = tid * CH + (int)sm->esel[tid];
        int pend = min((tid + 1) * CH, NP);
        int nv = 0;
        int* hw = sm->histW[wid];

        #pragma unroll 1
        for (int it = 0; it < 6; it++) {
            int key0 = 66, key1 = 66, key2 = 66, key3 = 66;
            if (p < pend) {
                int u1 = (int)sm->nxt[p];
                int u2 = (int)sm->nxt2[p];
                {
                    int qn = p + u1;
                    int j = min(3 * qn, LDIM);
                    int len = j - 3 * p;
                    int S = (int)sm->cs3[qn] - (int)sm->cs3[p];
                    nv++;
                    if (len == 3) key0 = S; else if (len == 12) key0 = 16 + S;
                    else { sm->tailS = S; sm->tailLen = len; }
                }
                int p1 = p + u1;
                if (p1 < pend) {
                    int ul = u2 - u1;
                    int qn = p1 + ul;
                    int j = min(3 * qn, LDIM);
                    int len = j - 3 * p1;
                    int S = (int)sm->cs3[qn] - (int)sm->cs3[p1];
                    nv++;
                    if (len == 3) key1 = S; else if (len == 12) key1 = 16 + S;
                    else { sm->tailS = S; sm->tailLen = len; }
                    int p2 = p + u2;
                    if (p2 < pend) {
                        int u3 = (int)sm->nxt[p2];
                        int u4 = (int)sm->nxt2[p2];
                        {
                            int qn2 = p2 + u3;
                            int j2 = min(3 * qn2, LDIM);
                            int len2 = j2 - 3 * p2;
                            int S2 = (int)sm->cs3[qn2] - (int)sm->cs3[p2];
                            nv++;
                            if (len2 == 3) key2 = S2; else if (len2 == 12) key2 = 16 + S2;
                            else { sm->tailS = S2; sm->tailLen = len2; }
                        }
                        int p3 = p2 + u3;
                        if (p3 < pend) {
                            int ul2 = u4 - u3;
                            int qn3 = p3 + ul2;
                            int j3 = min(3 * qn3, LDIM);
                            int len3 = j3 - 3 * p3;
                            int S3 = (int)sm->cs3[qn3] - (int)sm->cs3[p3];
                            nv++;
                            if (len3 == 3) key3 = S3; else if (len3 == 12) key3 = 16 + S3;
                            else { sm->tailS = S3; sm->tailLen = len3; }
                            p = p2 + u4;
                        } else p = p3;
                    } else p = p2;
                } else p = p1;
            }
            unsigned int g;
            g = __match_any_sync(0xffffffffu, key0);
            if (key0 != 66 && (__ffs(g) - 1) == lane) hw[key0] += __popc(g);
            g = __match_any_sync(0xffffffffu, key1);
            if (key1 != 66 && (__ffs(g) - 1) == lane) hw[key1] += __popc(g);
            g = __match_any_sync(0xffffffffu, key2);
            if (key2 != 66 && (__ffs(g) - 1) == lane) hw[key2] += __popc(g);
            g = __match_any_sync(0xffffffffu, key3);
            if (key3 != 66 && (__ffs(g) - 1) == lane) hw[key3] += __popc(g);
        }
        #pragma unroll
        for (int d = 16; d > 0; d >>= 1) nv += __shfl_down_sync(0xffffffffu, nv, d);
        if (lane == 0) sm->NvW[wid] = nv;
    }
    asm volatile("cp.async.wait_group 0;\n" ::: "memory");
    __syncthreads();

    // ---- hsum[e] = mean over valid patches of relu(mean*w1[e]+b1[e]) ----
    // (reads all 4 per-warp histograms directly — R5-proven pattern, saves a phase)
    if (tid < EDIM) {
        float acc = 0.0f;
        #pragma unroll
        for (int s = 0; s <= 12; s++) {
            int c = sm->histW[0][s] + sm->histW[1][s] + sm->histW[2][s] + sm->histW[3][s];
            acc += (float)c * fmaxf(fmaf((float)s / 3.0f, wv1, bv1), 0.0f);
        }
        #pragma unroll
        for (int s = 0; s <= 48; s++) {
            int c = sm->histW[0][16 + s] + sm->histW[1][16 + s] +
                    sm->histW[2][16 + s] + sm->histW[3][16 + s];
            acc += (float)c * fmaxf(fmaf((float)s / 12.0f, wv1, bv1), 0.0f);
        }
        if (sm->tailLen > 0)
            acc += fmaxf(fmaf((float)sm->tailS / (float)sm->tailLen, wv1, bv1), 0.0f);
        int Nv = sm->NvW[0] + sm->NvW[1] + sm->NvW[2] + sm->NvW[3];
        sm->hsum[tid] = acc / (float)Nv;
    }
    __syncthreads();

    // ---- vec = hbar @ w2^T + b2 ----
    if (tid < EDIM) {
        const float* wrow = sm->w2s + tid * 65;
        float v = bv2;
        #pragma unroll
        for (int e = 0; e < EDIM; e++) v = fmaf(sm->hsum[e], wrow[e], v);
        out[(size_t)row * EDIM + tid] = v;
    }
}

extern "C" void kernel_launch(void* const* d_in, const int* in_sizes, int n_in,
                              void* d_out, int out_size)
{
    const int*   x  = (const int*)d_in[0];
    const float* w1 = (const float*)d_in[1];
    const float* b1 = (const float*)d_in[2];
    const float* w2 = (const float*)d_in[3];
    const float* b2 = (const float*)d_in[4];
    float* out = (float*)d_out;

    cudaFuncSetAttribute(ep_kernel, cudaFuncAttributeMaxDynamicSharedMemorySize,
                         (int)sizeof(SmemLayout));
    ep_kernel<<<BDIM, NTHREADS, sizeof(SmemLayout)>>>(x, w1, b1, w2, b2, out);
}